// round 4
// baseline (speedup 1.0000x reference)
#include <cuda_runtime.h>

#define BB 8
#define TT 2048
#define CC 1024
#define HH 64
#define SCALE 0.03125f   // C^-0.5 = 1/32

// Scratch (static device globals: no allocation allowed)
__device__ float g_q[BB * TT * HH];
__device__ float g_k[BB * TT * HH];
__device__ float g_v[BB * TT * HH];

// ---------------------------------------------------------------------------
// QKV projection: X[16384,1024] @ W[1024,64] -> out[16384,64], one W per
// blockIdx.y. 128x64 block tile, 8x4 per-thread microtile, K-tiles of 16.
// ---------------------------------------------------------------------------
__global__ __launch_bounds__(256) void qkv_gemm(
    const float* __restrict__ x, const float* __restrict__ Wq,
    const float* __restrict__ Wk, const float* __restrict__ Wv)
{
    __shared__ float As[16][129];   // [k][m], padded to kill write conflicts
    __shared__ float Bs[16][64];    // [k][n]

    const float* W   = (blockIdx.y == 0) ? Wq : (blockIdx.y == 1) ? Wk : Wv;
    float*       dst = (blockIdx.y == 0) ? g_q : (blockIdx.y == 1) ? g_k : g_v;

    const int tid = threadIdx.x;
    const int tx  = tid & 15;        // 0..15 -> N
    const int ty  = tid >> 4;        // 0..15 -> M
    const int mBase = blockIdx.x * 128;

    float acc[8][4];
#pragma unroll
    for (int i = 0; i < 8; i++)
#pragma unroll
        for (int j = 0; j < 4; j++) acc[i][j] = 0.0f;

    for (int k0 = 0; k0 < CC; k0 += 16) {
#pragma unroll
        for (int i = 0; i < 8; i++) {
            int idx = tid + i * 256;                 // 0..2047
            int m = idx >> 4, k = idx & 15;
            As[k][m] = x[(mBase + m) * CC + k0 + k];
        }
#pragma unroll
        for (int i = 0; i < 4; i++) {
            int idx = tid + i * 256;                 // 0..1023
            int k = idx >> 6, h = idx & 63;
            Bs[k][h] = W[(k0 + k) * HH + h];
        }
        __syncthreads();
#pragma unroll
        for (int kk = 0; kk < 16; kk++) {
            float a[8], b[4];
#pragma unroll
            for (int i = 0; i < 8; i++) a[i] = As[kk][ty + i * 16];
#pragma unroll
            for (int j = 0; j < 4; j++) b[j] = Bs[kk][tx + j * 16];
#pragma unroll
            for (int i = 0; i < 8; i++)
#pragma unroll
                for (int j = 0; j < 4; j++) acc[i][j] += a[i] * b[j];
        }
        __syncthreads();
    }
#pragma unroll
    for (int i = 0; i < 8; i++)
#pragma unroll
        for (int j = 0; j < 4; j++)
            dst[(mBase + ty + i * 16) * HH + tx + j * 16] = acc[i][j];
}

// ---------------------------------------------------------------------------
// Flash attention with resonance bias/mask.
// Block = (qtile of 64, batch). 256 threads as 16x16; thread owns a 4x4
// microtile (rows ty+i*16, cols tx+j*16). SMEM: Q, K/P (shared buffer), V,
// XOR-swizzled rows for bank-conflict-free access. 48KB static exactly.
// allowed(i,j) == (j<i && rbias>0) || (i==j); score = qk*scale + rbias.
// ---------------------------------------------------------------------------
__global__ __launch_bounds__(256) void attn(
    const float* __restrict__ rbias, float* __restrict__ outp)
{
    __shared__ float Qs[64 * 64];    // row r, col h at r*64 + (h ^ (r&31))
    __shared__ float KPs[64 * 64];   // K rows (c,h) then reused for P rows (r,c)
    __shared__ float Vs[64 * 64];    // plain row-major [c][d]

    const int tid = threadIdx.x;
    const int tx  = tid & 15;
    const int ty  = tid >> 4;
    const int b   = blockIdx.y;
    const int qt  = blockIdx.x;
    const int qBase = qt * 64;

    // ---- load Q tile (pre-scaled) ----
    const float* qp = g_q + (b * TT + qBase) * HH;
#pragma unroll
    for (int i = 0; i < 16; i++) {
        int idx = tid + i * 256;           // 0..4095
        int r = idx >> 6, h = idx & 63;
        Qs[r * 64 + (h ^ (r & 31))] = qp[idx] * SCALE;
    }

    float m_i[4], l_i[4], acc[4][4];
#pragma unroll
    for (int i = 0; i < 4; i++) {
        m_i[i] = -1e30f; l_i[i] = 0.0f;
#pragma unroll
        for (int j = 0; j < 4; j++) acc[i][j] = 0.0f;
    }

    int qrb[4], qrm[4], krb[4], krm[4];
#pragma unroll
    for (int i = 0; i < 4; i++) {
        int r = ty + i * 16; qrb[i] = r * 64; qrm[i] = r & 31;
        int c = tx + i * 16; krb[i] = c * 64; krm[i] = c & 31;
    }

    for (int kt = 0; kt <= qt; kt++) {
        const int kBase = kt * 64;
        const float* kp = g_k + (b * TT + kBase) * HH;
        const float* vp = g_v + (b * TT + kBase) * HH;

        __syncthreads();   // protect K/V (read last iter) before overwrite
#pragma unroll
        for (int i = 0; i < 16; i++) {
            int idx = tid + i * 256;
            int c = idx >> 6, h = idx & 63;
            KPs[c * 64 + (h ^ (c & 31))] = kp[idx];
            Vs[idx] = vp[idx];
        }
        __syncthreads();

        // ---- S = (Q*scale) @ K^T ----
        float s[4][4];
#pragma unroll
        for (int i = 0; i < 4; i++)
#pragma unroll
            for (int j = 0; j < 4; j++) s[i][j] = 0.0f;
#pragma unroll
        for (int h = 0; h < 64; h++) {
            float a[4], kv[4];
#pragma unroll
            for (int i = 0; i < 4; i++) a[i]  = Qs[qrb[i] + (h ^ qrm[i])];
#pragma unroll
            for (int j = 0; j < 4; j++) kv[j] = KPs[krb[j] + (h ^ krm[j])];
#pragma unroll
            for (int i = 0; i < 4; i++)
#pragma unroll
                for (int j = 0; j < 4; j++) s[i][j] += a[i] * kv[j];
        }

        // ---- bias + mask ----
#pragma unroll
        for (int i = 0; i < 4; i++) {
            int gi = qBase + ty + i * 16;
#pragma unroll
            for (int j = 0; j < 4; j++) {
                int gj = kBase + tx + j * 16;
                float rb = rbias[gi * TT + gj];
                bool ok = (gj == gi) || (gj < gi && rb > 0.0f);
                s[i][j] = ok ? (s[i][j] + rb) : -1e30f;
            }
        }

        // ---- online softmax (rows shared by 16-lane groups with same ty) ----
#pragma unroll
        for (int i = 0; i < 4; i++) {
            float mx = fmaxf(fmaxf(s[i][0], s[i][1]), fmaxf(s[i][2], s[i][3]));
            mx = fmaxf(mx, __shfl_xor_sync(0xffffffffu, mx, 8));
            mx = fmaxf(mx, __shfl_xor_sync(0xffffffffu, mx, 4));
            mx = fmaxf(mx, __shfl_xor_sync(0xffffffffu, mx, 2));
            mx = fmaxf(mx, __shfl_xor_sync(0xffffffffu, mx, 1));
            float mn   = fmaxf(m_i[i], mx);
            float corr = __expf(m_i[i] - mn);   // exp(0)=1 when both -1e30: safe
            m_i[i] = mn;
            float p[4], rs = 0.0f;
#pragma unroll
            for (int j = 0; j < 4; j++) {
                // guard: fully-masked entries must contribute exactly 0 even
                // when mn is still -1e30 (exp(0)=1 trap)
                p[j] = (s[i][j] < -1e29f) ? 0.0f : __expf(s[i][j] - mn);
                rs += p[j];
            }
            rs += __shfl_xor_sync(0xffffffffu, rs, 8);
            rs += __shfl_xor_sync(0xffffffffu, rs, 4);
            rs += __shfl_xor_sync(0xffffffffu, rs, 2);
            rs += __shfl_xor_sync(0xffffffffu, rs, 1);
            l_i[i] = l_i[i] * corr + rs;
#pragma unroll
            for (int j = 0; j < 4; j++) acc[i][j] *= corr;
            // write P into the K buffer (K is dead now): row=q-row, col=key
#pragma unroll
            for (int j = 0; j < 4; j++)
                KPs[qrb[i] + ((tx + j * 16) ^ qrm[i])] = p[j];
        }
        __syncthreads();

        // ---- O += P @ V ----
#pragma unroll
        for (int c = 0; c < 64; c++) {
            float a[4], vv[4];
#pragma unroll
            for (int i = 0; i < 4; i++) a[i]  = KPs[qrb[i] + (c ^ qrm[i])];
#pragma unroll
            for (int j = 0; j < 4; j++) vv[j] = Vs[c * 64 + tx + j * 16];
#pragma unroll
            for (int i = 0; i < 4; i++)
#pragma unroll
                for (int j = 0; j < 4; j++) acc[i][j] += a[i] * vv[j];
        }
    }

    // ---- epilogue: normalize and store ----
#pragma unroll
    for (int i = 0; i < 4; i++) {
        float inv = 1.0f / l_i[i];
        int gi = qBase + ty + i * 16;
#pragma unroll
        for (int j = 0; j < 4; j++)
            outp[(b * TT + gi) * HH + tx + j * 16] = acc[i][j] * inv;
    }
}

// ---------------------------------------------------------------------------
extern "C" void kernel_launch(void* const* d_in, const int* in_sizes, int n_in,
                              void* d_out, int out_size)
{
    const float* x     = (const float*)d_in[0];
    const float* Wq    = (const float*)d_in[1];
    const float* Wk    = (const float*)d_in[2];
    const float* Wv    = (const float*)d_in[3];
    const float* rbias = (const float*)d_in[4];
    // d_in[5] = allowed: unused, reconstructed from rbias + diagonal + causal
    float* outp = (float*)d_out;

    qkv_gemm<<<dim3(128, 3), 256>>>(x, Wq, Wk, Wv);
    attn<<<dim3(32, 8), 256>>>(rbias, outp);
}

// round 5
// speedup vs baseline: 1.6484x; 1.6484x over previous
#include <cuda_runtime.h>

#define BB 8
#define TT 2048
#define CC 1024
#define HH 64
#define SCALE 0.03125f   // C^-0.5 = 1/32

// Scratch (static device globals: no allocation allowed)
__device__ float g_q[BB * TT * HH];
__device__ float g_k[BB * TT * HH];
__device__ float g_v[BB * TT * HH];

// ---------------- packed f32x2 helpers (Blackwell FFMA2 path) ----------------
typedef unsigned long long ull;

__device__ __forceinline__ ull f2pk(float lo, float hi) {
    ull r; asm("mov.b64 %0, {%1, %2};" : "=l"(r) : "f"(lo), "f"(hi)); return r;
}
__device__ __forceinline__ ull fdup(float v) { return f2pk(v, v); }
__device__ __forceinline__ void f2up(ull v, float& lo, float& hi) {
    asm("mov.b64 {%0, %1}, %2;" : "=f"(lo), "=f"(hi) : "l"(v));
}
__device__ __forceinline__ void fma2(ull& d, ull a, ull b) {
    asm("fma.rn.f32x2 %0, %1, %2, %0;" : "+l"(d) : "l"(a), "l"(b));
}
__device__ __forceinline__ void mul2(ull& d, ull c) {
    asm("mul.rn.f32x2 %0, %0, %1;" : "+l"(d) : "l"(c));
}

// ---------------------------------------------------------------------------
// Fused QKV projection: X[16384,1024] @ {Wq,Wk,Wv}[1024,64].
// One block = 128 M-rows x all 64 N for all THREE weights (x tile loaded once).
// 256 threads: ty=tid>>4 owns rows ty*8..ty*8+7; tx=tid&15 owns cols tx*4..+3
// (= 2 f32x2 pairs). Inner product via packed FFMA2.
// ---------------------------------------------------------------------------
__global__ __launch_bounds__(256) void qkv_gemm(
    const float* __restrict__ x, const float* __restrict__ Wq,
    const float* __restrict__ Wk, const float* __restrict__ Wv)
{
    __shared__ float  As[16 * 132];          // [k][m], padded rows (132 floats)
    __shared__ float4 Bs[3][16][16];         // [w][k][h4]

    const int tid = threadIdx.x;
    const int tx  = tid & 15;
    const int ty  = tid >> 4;
    const int mBase = blockIdx.x * 128;

    const float* __restrict__ Wp[3] = { Wq, Wk, Wv };

    ull acc2[8][3][2];
#pragma unroll
    for (int i = 0; i < 8; i++)
#pragma unroll
        for (int w = 0; w < 3; w++) { acc2[i][w][0] = 0ull; acc2[i][w][1] = 0ull; }

    const int kw  = tid >> 4;   // W row within k-tile (0..15)
    const int h4w = tid & 15;   // W float4 col

    for (int k0 = 0; k0 < CC; k0 += 16) {
        // prefetch to regs
        float4 xa[2], wb[3];
#pragma unroll
        for (int i = 0; i < 2; i++) {
            int idx = tid + i * 256;          // 0..511 float4s of the X tile
            int m = idx >> 2, k4 = idx & 3;
            xa[i] = *(const float4*)&x[(size_t)(mBase + m) * CC + k0 + k4 * 4];
        }
#pragma unroll
        for (int w = 0; w < 3; w++)
            wb[w] = *(const float4*)&Wp[w][(size_t)(k0 + kw) * HH + h4w * 4];

        __syncthreads();
#pragma unroll
        for (int i = 0; i < 2; i++) {
            int idx = tid + i * 256;
            int m = idx >> 2, k4 = idx & 3;
            As[(k4 * 4 + 0) * 132 + m] = xa[i].x;
            As[(k4 * 4 + 1) * 132 + m] = xa[i].y;
            As[(k4 * 4 + 2) * 132 + m] = xa[i].z;
            As[(k4 * 4 + 3) * 132 + m] = xa[i].w;
        }
#pragma unroll
        for (int w = 0; w < 3; w++) Bs[w][kw][h4w] = wb[w];
        __syncthreads();

#pragma unroll
        for (int kk = 0; kk < 16; kk++) {
            float4 a0 = *(const float4*)&As[kk * 132 + ty * 8];
            float4 a1 = *(const float4*)&As[kk * 132 + ty * 8 + 4];
            ull ad[8];
            ad[0] = fdup(a0.x); ad[1] = fdup(a0.y); ad[2] = fdup(a0.z); ad[3] = fdup(a0.w);
            ad[4] = fdup(a1.x); ad[5] = fdup(a1.y); ad[6] = fdup(a1.z); ad[7] = fdup(a1.w);
#pragma unroll
            for (int w = 0; w < 3; w++) {
                float4 b4 = Bs[w][kk][tx];
                ull b01 = f2pk(b4.x, b4.y);
                ull b23 = f2pk(b4.z, b4.w);
#pragma unroll
                for (int i = 0; i < 8; i++) {
                    fma2(acc2[i][w][0], ad[i], b01);
                    fma2(acc2[i][w][1], ad[i], b23);
                }
            }
        }
        __syncthreads();
    }

    float* dsts[3] = { g_q, g_k, g_v };
#pragma unroll
    for (int w = 0; w < 3; w++) {
#pragma unroll
        for (int i = 0; i < 8; i++) {
            float4 v;
            f2up(acc2[i][w][0], v.x, v.y);
            f2up(acc2[i][w][1], v.z, v.w);
            *(float4*)&dsts[w][(size_t)(mBase + ty * 8 + i) * HH + tx * 4] = v;
        }
    }
}

// ---------------------------------------------------------------------------
// Flash attention, f32x2 + vectorized SMEM.
// Block = (pair-of-qtiles, batch). Pairing qt with 31-qt => every block does
// exactly 33 tile-iters (perfect balance). 256 threads; thread owns rows
// ty+i*16 (i<4) and cols tx*4..tx*4+3 (2 f32x2 pairs).
// Layouts: Qs[r][h4] plain f4; Kt[h][g] transposed, g = c4 ^ (h>>2 & 15);
// Vs[c][d4] plain; P reuses Kt buffer as [r][c4] plain.
// ---------------------------------------------------------------------------
__global__ __launch_bounds__(256) void attn(
    const float* __restrict__ rbias, float* __restrict__ outp)
{
    __shared__ float4 Qs[1024];   // 16 KB
    __shared__ float4 KtP[1024];  // 16 KB  (K^T, then P)
    __shared__ float4 Vs[1024];   // 16 KB
    float* KtPf = (float*)KtP;

    const int tid = threadIdx.x;
    const int tx  = tid & 15;
    const int ty  = tid >> 4;
    const int b   = blockIdx.y;

    int r_[4];
#pragma unroll
    for (int i = 0; i < 4; i++) r_[i] = ty + i * 16;

#pragma unroll 1
    for (int pass = 0; pass < 2; pass++) {
        const int qt = pass ? (31 - blockIdx.x) : blockIdx.x;
        const int qBase = qt * 64;

        __syncthreads();   // previous pass fully done before Q overwrite
        const float4* qp = (const float4*)(g_q + (size_t)(b * TT + qBase) * HH);
#pragma unroll
        for (int i = 0; i < 4; i++) {
            int idx = tid + i * 256;
            float4 v = qp[idx];
            v.x *= SCALE; v.y *= SCALE; v.z *= SCALE; v.w *= SCALE;
            Qs[idx] = v;
        }

        float m_i[4], l_i[4];
        ull o2[4][2];
#pragma unroll
        for (int i = 0; i < 4; i++) {
            m_i[i] = -1e30f; l_i[i] = 0.0f; o2[i][0] = 0ull; o2[i][1] = 0ull;
        }

#pragma unroll 1
        for (int kt = 0; kt <= qt; kt++) {
            const int kBase = kt * 64;
            const float4* kp = (const float4*)(g_k + (size_t)(b * TT + kBase) * HH);
            const float4* vp = (const float4*)(g_v + (size_t)(b * TT + kBase) * HH);

            float4 kreg[4], vreg[4];
#pragma unroll
            for (int i = 0; i < 4; i++) {
                int idx = tid + i * 256;
                kreg[i] = kp[idx]; vreg[i] = vp[idx];
            }
            __syncthreads();   // prev-iter P/V reads done (and Q ready, iter 0)
#pragma unroll
            for (int i = 0; i < 4; i++) {
                int idx = tid + i * 256;
                int c = idx >> 4, h4g = idx & 15;
                Vs[idx] = vreg[i];
                int base = (((c >> 2) ^ h4g) << 2) + (c & 3);   // swizzled slot
                KtPf[(h4g * 4 + 0) * 64 + base] = kreg[i].x;
                KtPf[(h4g * 4 + 1) * 64 + base] = kreg[i].y;
                KtPf[(h4g * 4 + 2) * 64 + base] = kreg[i].z;
                KtPf[(h4g * 4 + 3) * 64 + base] = kreg[i].w;
            }
            __syncthreads();

            // ---- S = Q @ K^T (packed pairs over key-columns) ----
            ull s2[4][2];
#pragma unroll
            for (int i = 0; i < 4; i++) { s2[i][0] = 0ull; s2[i][1] = 0ull; }

#pragma unroll 4
            for (int h4 = 0; h4 < 16; h4++) {
                float4 q0 = Qs[r_[0] * 16 + h4];
                float4 q1 = Qs[r_[1] * 16 + h4];
                float4 q2 = Qs[r_[2] * 16 + h4];
                float4 q3 = Qs[r_[3] * 16 + h4];
                int kb = tx ^ h4;
                float4 kv0 = KtP[(h4 * 4 + 0) * 16 + kb];
                float4 kv1 = KtP[(h4 * 4 + 1) * 16 + kb];
                float4 kv2 = KtP[(h4 * 4 + 2) * 16 + kb];
                float4 kv3 = KtP[(h4 * 4 + 3) * 16 + kb];
#define SB(KC, QM) { ull b01 = f2pk(KC.x, KC.y), b23 = f2pk(KC.z, KC.w); ull qq; \
                qq = fdup(q0.QM); fma2(s2[0][0], qq, b01); fma2(s2[0][1], qq, b23); \
                qq = fdup(q1.QM); fma2(s2[1][0], qq, b01); fma2(s2[1][1], qq, b23); \
                qq = fdup(q2.QM); fma2(s2[2][0], qq, b01); fma2(s2[2][1], qq, b23); \
                qq = fdup(q3.QM); fma2(s2[3][0], qq, b01); fma2(s2[3][1], qq, b23); }
                SB(kv0, x) SB(kv1, y) SB(kv2, z) SB(kv3, w)
#undef SB
            }

            float s[4][4];
#pragma unroll
            for (int i = 0; i < 4; i++) {
                f2up(s2[i][0], s[i][0], s[i][1]);
                f2up(s2[i][1], s[i][2], s[i][3]);
            }
            __syncthreads();   // ALL warps done reading K before P overwrites it

            // ---- bias + mask + online softmax + P write ----
#pragma unroll
            for (int i = 0; i < 4; i++) {
                int gi = qBase + r_[i];
                float4 rb = *(const float4*)(rbias + (size_t)gi * TT + kBase + tx * 4);
                float rbv[4] = { rb.x, rb.y, rb.z, rb.w };
#pragma unroll
                for (int j = 0; j < 4; j++) {
                    int gj = kBase + tx * 4 + j;
                    bool ok = (gj == gi) || (gj < gi && rbv[j] > 0.0f);
                    s[i][j] = ok ? (s[i][j] + rbv[j]) : -1e30f;
                }
                float mx = fmaxf(fmaxf(s[i][0], s[i][1]), fmaxf(s[i][2], s[i][3]));
                mx = fmaxf(mx, __shfl_xor_sync(0xffffffffu, mx, 8));
                mx = fmaxf(mx, __shfl_xor_sync(0xffffffffu, mx, 4));
                mx = fmaxf(mx, __shfl_xor_sync(0xffffffffu, mx, 2));
                mx = fmaxf(mx, __shfl_xor_sync(0xffffffffu, mx, 1));
                float mn   = fmaxf(m_i[i], mx);
                float corr = __expf(m_i[i] - mn);
                m_i[i] = mn;
                float p[4], rs = 0.0f;
#pragma unroll
                for (int j = 0; j < 4; j++) {
                    p[j] = (s[i][j] < -1e29f) ? 0.0f : __expf(s[i][j] - mn);
                    rs += p[j];
                }
                rs += __shfl_xor_sync(0xffffffffu, rs, 8);
                rs += __shfl_xor_sync(0xffffffffu, rs, 4);
                rs += __shfl_xor_sync(0xffffffffu, rs, 2);
                rs += __shfl_xor_sync(0xffffffffu, rs, 1);
                l_i[i] = l_i[i] * corr + rs;
                ull cd = fdup(corr);
                mul2(o2[i][0], cd); mul2(o2[i][1], cd);
                float4 pv = make_float4(p[0], p[1], p[2], p[3]);
                KtP[r_[i] * 16 + tx] = pv;          // P[r][c4] plain
            }
            __syncthreads();   // full P rows visible before PV

            // ---- O += P @ V (packed pairs over head-dim) ----
#pragma unroll 4
            for (int c4 = 0; c4 < 16; c4++) {
                float4 p0 = KtP[r_[0] * 16 + c4];
                float4 p1 = KtP[r_[1] * 16 + c4];
                float4 p2 = KtP[r_[2] * 16 + c4];
                float4 p3 = KtP[r_[3] * 16 + c4];
                float4 v0 = Vs[(c4 * 4 + 0) * 16 + tx];
                float4 v1 = Vs[(c4 * 4 + 1) * 16 + tx];
                float4 v2 = Vs[(c4 * 4 + 2) * 16 + tx];
                float4 v3 = Vs[(c4 * 4 + 3) * 16 + tx];
#define PB(VC, PM) { ull b01 = f2pk(VC.x, VC.y), b23 = f2pk(VC.z, VC.w); ull pp; \
                pp = fdup(p0.PM); fma2(o2[0][0], pp, b01); fma2(o2[0][1], pp, b23); \
                pp = fdup(p1.PM); fma2(o2[1][0], pp, b01); fma2(o2[1][1], pp, b23); \
                pp = fdup(p2.PM); fma2(o2[2][0], pp, b01); fma2(o2[2][1], pp, b23); \
                pp = fdup(p3.PM); fma2(o2[3][0], pp, b01); fma2(o2[3][1], pp, b23); }
                PB(v0, x) PB(v1, y) PB(v2, z) PB(v3, w)
#undef PB
            }
        }

        // ---- epilogue ----
#pragma unroll
        for (int i = 0; i < 4; i++) {
            float inv = 1.0f / l_i[i];
            float4 v;
            f2up(o2[i][0], v.x, v.y);
            f2up(o2[i][1], v.z, v.w);
            v.x *= inv; v.y *= inv; v.z *= inv; v.w *= inv;
            *(float4*)&outp[(size_t)(b * TT + qBase + r_[i]) * HH + tx * 4] = v;
        }
    }
}

// ---------------------------------------------------------------------------
extern "C" void kernel_launch(void* const* d_in, const int* in_sizes, int n_in,
                              void* d_out, int out_size)
{
    const float* x     = (const float*)d_in[0];
    const float* Wq    = (const float*)d_in[1];
    const float* Wk    = (const float*)d_in[2];
    const float* Wv    = (const float*)d_in[3];
    const float* rbias = (const float*)d_in[4];
    // d_in[5] = allowed: reconstructed from rbias + diagonal + causal
    float* outp = (float*)d_out;

    qkv_gemm<<<128, 256>>>(x, Wq, Wk, Wv);
    attn<<<dim3(16, 8), 256>>>(rbias, outp);
}

// round 9
// speedup vs baseline: 2.0372x; 1.2358x over previous
#include <cuda_runtime.h>

#define BB 8
#define TT 2048
#define CC 1024
#define HH 64
#define SCALE 0.03125f            // C^-0.5 = 1/32
#define L2E   1.4426950408889634f // log2(e)

// Scratch (static device globals: no allocation allowed)
__device__ float g_q[BB * TT * HH];    // pre-scaled by SCALE*L2E
__device__ float g_k[BB * TT * HH];
__device__ float g_v[BB * TT * HH];
__device__ float g_po[2][BB * TT * HH]; // unnormalized partial O per z-split
__device__ float g_l [2][BB * TT];      // partial row sums per z-split

// ---------------- packed f32x2 helpers (Blackwell FFMA2 path) ----------------
typedef unsigned long long ull;

__device__ __forceinline__ ull f2pk(float lo, float hi) {
    ull r; asm("mov.b64 %0, {%1, %2};" : "=l"(r) : "f"(lo), "f"(hi)); return r;
}
__device__ __forceinline__ ull fdup(float v) { return f2pk(v, v); }
__device__ __forceinline__ void f2up(ull v, float& lo, float& hi) {
    asm("mov.b64 {%0, %1}, %2;" : "=f"(lo), "=f"(hi) : "l"(v));
}
__device__ __forceinline__ void fma2(ull& d, ull a, ull b) {
    asm("fma.rn.f32x2 %0, %1, %2, %0;" : "+l"(d) : "l"(a), "l"(b));
}
__device__ __forceinline__ float ex2(float x) {
    float r; asm("ex2.approx.f32 %0, %1;" : "=f"(r) : "f"(x)); return r;
}

// ---------------------------------------------------------------------------
// Fused QKV projection: X[16384,1024] @ {Wq,Wk,Wv}[1024,64].
// Q output is pre-scaled by SCALE*L2E so attention scores are in log2 units.
// ---------------------------------------------------------------------------
__global__ __launch_bounds__(256) void qkv_gemm(
    const float* __restrict__ x, const float* __restrict__ Wq,
    const float* __restrict__ Wk, const float* __restrict__ Wv)
{
    __shared__ float  As[16 * 132];          // [k][m], padded rows
    __shared__ float4 Bs[3][16][16];         // [w][k][h4]

    const int tid = threadIdx.x;
    const int tx  = tid & 15;
    const int ty  = tid >> 4;
    const int mBase = blockIdx.x * 128;

    const float* __restrict__ Wp[3] = { Wq, Wk, Wv };

    ull acc2[8][3][2];
#pragma unroll
    for (int i = 0; i < 8; i++)
#pragma unroll
        for (int w = 0; w < 3; w++) { acc2[i][w][0] = 0ull; acc2[i][w][1] = 0ull; }

    const int kw  = tid >> 4;
    const int h4w = tid & 15;

    for (int k0 = 0; k0 < CC; k0 += 16) {
        float4 xa[2], wb[3];
#pragma unroll
        for (int i = 0; i < 2; i++) {
            int idx = tid + i * 256;
            int m = idx >> 2, k4 = idx & 3;
            xa[i] = *(const float4*)&x[(size_t)(mBase + m) * CC + k0 + k4 * 4];
        }
#pragma unroll
        for (int w = 0; w < 3; w++)
            wb[w] = *(const float4*)&Wp[w][(size_t)(k0 + kw) * HH + h4w * 4];

        __syncthreads();
#pragma unroll
        for (int i = 0; i < 2; i++) {
            int idx = tid + i * 256;
            int m = idx >> 2, k4 = idx & 3;
            As[(k4 * 4 + 0) * 132 + m] = xa[i].x;
            As[(k4 * 4 + 1) * 132 + m] = xa[i].y;
            As[(k4 * 4 + 2) * 132 + m] = xa[i].z;
            As[(k4 * 4 + 3) * 132 + m] = xa[i].w;
        }
#pragma unroll
        for (int w = 0; w < 3; w++) Bs[w][kw][h4w] = wb[w];
        __syncthreads();

#pragma unroll
        for (int kk = 0; kk < 16; kk++) {
            float4 a0 = *(const float4*)&As[kk * 132 + ty * 8];
            float4 a1 = *(const float4*)&As[kk * 132 + ty * 8 + 4];
            ull ad[8];
            ad[0] = fdup(a0.x); ad[1] = fdup(a0.y); ad[2] = fdup(a0.z); ad[3] = fdup(a0.w);
            ad[4] = fdup(a1.x); ad[5] = fdup(a1.y); ad[6] = fdup(a1.z); ad[7] = fdup(a1.w);
#pragma unroll
            for (int w = 0; w < 3; w++) {
                float4 b4 = Bs[w][kk][tx];
                ull b01 = f2pk(b4.x, b4.y);
                ull b23 = f2pk(b4.z, b4.w);
#pragma unroll
                for (int i = 0; i < 8; i++) {
                    fma2(acc2[i][w][0], ad[i], b01);
                    fma2(acc2[i][w][1], ad[i], b23);
                }
            }
        }
        __syncthreads();
    }

    float* dsts[3] = { g_q, g_k, g_v };
    const float QSCL = SCALE * L2E;
#pragma unroll
    for (int w = 0; w < 3; w++) {
#pragma unroll
        for (int i = 0; i < 8; i++) {
            float4 v;
            f2up(acc2[i][w][0], v.x, v.y);
            f2up(acc2[i][w][1], v.z, v.w);
            if (w == 0) { v.x *= QSCL; v.y *= QSCL; v.z *= QSCL; v.w *= QSCL; }
            *(float4*)&dsts[w][(size_t)(mBase + ty * 8 + i) * HH + tx * 4] = v;
        }
    }
}

// ---------------------------------------------------------------------------
// Flash attention, fixed-reference (no-max) softmax in log2 units, split-K.
// Block = (pair-of-qtiles bx, batch b, parity z). z handles kt = z, z+2, ...
// Pairing qt=bx with qt=31-bx => every block does ~16.5 kt-iters. Partials are
// ADDITIVE (no max-merge): O_part, l_part -> scratch; combine kernel divides.
// ---------------------------------------------------------------------------
__global__ __launch_bounds__(256) void attn(const float* __restrict__ rbias)
{
    __shared__ float4 Qs[1024];   // 16 KB
    __shared__ float4 KtP[1024];  // 16 KB  (K^T swizzled, then P)
    __shared__ float4 Vs[1024];   // 16 KB
    float* KtPf = (float*)KtP;

    const int tid = threadIdx.x;
    const int tx  = tid & 15;
    const int ty  = tid >> 4;
    const int b   = blockIdx.y;
    const int z   = blockIdx.z;

    int r_[4];
#pragma unroll
    for (int i = 0; i < 4; i++) r_[i] = ty + i * 16;

#pragma unroll 1
    for (int pass = 0; pass < 2; pass++) {
        const int qt = pass ? (31 - blockIdx.x) : blockIdx.x;
        const int qBase = qt * 64;

        __syncthreads();   // previous pass fully done before Q overwrite
        const float4* qp = (const float4*)(g_q + (size_t)(b * TT + qBase) * HH);
#pragma unroll
        for (int i = 0; i < 4; i++) {
            int idx = tid + i * 256;
            Qs[idx] = qp[idx];      // already scaled to log2 units
        }

        float l_i[4];
        ull o2[4][2];
#pragma unroll
        for (int i = 0; i < 4; i++) { l_i[i] = 0.0f; o2[i][0] = 0ull; o2[i][1] = 0ull; }

#pragma unroll 1
        for (int kt = z; kt <= qt; kt += 2) {
            const int kBase = kt * 64;
            const float4* kp = (const float4*)(g_k + (size_t)(b * TT + kBase) * HH);
            const float4* vp = (const float4*)(g_v + (size_t)(b * TT + kBase) * HH);

            float4 kreg[4], vreg[4];
#pragma unroll
            for (int i = 0; i < 4; i++) {
                int idx = tid + i * 256;
                kreg[i] = kp[idx]; vreg[i] = vp[idx];
            }
            __syncthreads();   // prev-iter P/V reads done (and Q ready, iter 0)
#pragma unroll
            for (int i = 0; i < 4; i++) {
                int idx = tid + i * 256;
                int c = idx >> 4, h4g = idx & 15;
                Vs[idx] = vreg[i];
                int base = (((c >> 2) ^ h4g) << 2) + (c & 3);   // swizzled slot
                KtPf[(h4g * 4 + 0) * 64 + base] = kreg[i].x;
                KtPf[(h4g * 4 + 1) * 64 + base] = kreg[i].y;
                KtPf[(h4g * 4 + 2) * 64 + base] = kreg[i].z;
                KtPf[(h4g * 4 + 3) * 64 + base] = kreg[i].w;
            }
            __syncthreads();

            // ---- S = Q @ K^T (log2 units) ----
            ull s2[4][2];
#pragma unroll
            for (int i = 0; i < 4; i++) { s2[i][0] = 0ull; s2[i][1] = 0ull; }

#pragma unroll 4
            for (int h4 = 0; h4 < 16; h4++) {
                float4 q0 = Qs[r_[0] * 16 + h4];
                float4 q1 = Qs[r_[1] * 16 + h4];
                float4 q2 = Qs[r_[2] * 16 + h4];
                float4 q3 = Qs[r_[3] * 16 + h4];
                int kb = tx ^ h4;
                float4 kv0 = KtP[(h4 * 4 + 0) * 16 + kb];
                float4 kv1 = KtP[(h4 * 4 + 1) * 16 + kb];
                float4 kv2 = KtP[(h4 * 4 + 2) * 16 + kb];
                float4 kv3 = KtP[(h4 * 4 + 3) * 16 + kb];
#define SB(KC, QM) { ull b01 = f2pk(KC.x, KC.y), b23 = f2pk(KC.z, KC.w); ull qq; \
                qq = fdup(q0.QM); fma2(s2[0][0], qq, b01); fma2(s2[0][1], qq, b23); \
                qq = fdup(q1.QM); fma2(s2[1][0], qq, b01); fma2(s2[1][1], qq, b23); \
                qq = fdup(q2.QM); fma2(s2[2][0], qq, b01); fma2(s2[2][1], qq, b23); \
                qq = fdup(q3.QM); fma2(s2[3][0], qq, b01); fma2(s2[3][1], qq, b23); }
                SB(kv0, x) SB(kv1, y) SB(kv2, z) SB(kv3, w)
#undef SB
            }

            float s[4][4];
#pragma unroll
            for (int i = 0; i < 4; i++) {
                f2up(s2[i][0], s[i][0], s[i][1]);
                f2up(s2[i][1], s[i][2], s[i][3]);
            }
            __syncthreads();   // ALL warps done reading K before P overwrites it

            // ---- bias + mask + exp2 + local row-sum + P write ----
#pragma unroll
            for (int i = 0; i < 4; i++) {
                int gi = qBase + r_[i];
                float4 rb = *(const float4*)(rbias + (size_t)gi * TT + kBase + tx * 4);
                float rbv[4] = { rb.x, rb.y, rb.z, rb.w };
                float p[4];
#pragma unroll
                for (int j = 0; j < 4; j++) {
                    int gj = kBase + tx * 4 + j;
                    bool ok = (gj == gi) || (gj < gi && rbv[j] > 0.0f);
                    p[j] = ok ? ex2(fmaf(rbv[j], L2E, s[i][j])) : 0.0f;
                }
                l_i[i] += (p[0] + p[1]) + (p[2] + p[3]);
                KtP[r_[i] * 16 + tx] = make_float4(p[0], p[1], p[2], p[3]);
            }
            __syncthreads();   // full P rows visible before PV

            // ---- O += P @ V ----
#pragma unroll 4
            for (int c4 = 0; c4 < 16; c4++) {
                float4 p0 = KtP[r_[0] * 16 + c4];
                float4 p1 = KtP[r_[1] * 16 + c4];
                float4 p2 = KtP[r_[2] * 16 + c4];
                float4 p3 = KtP[r_[3] * 16 + c4];
                float4 v0 = Vs[(c4 * 4 + 0) * 16 + tx];
                float4 v1 = Vs[(c4 * 4 + 1) * 16 + tx];
                float4 v2 = Vs[(c4 * 4 + 2) * 16 + tx];
                float4 v3 = Vs[(c4 * 4 + 3) * 16 + tx];
#define PB(VC, PM) { ull b01 = f2pk(VC.x, VC.y), b23 = f2pk(VC.z, VC.w); ull pp; \
                pp = fdup(p0.PM); fma2(o2[0][0], pp, b01); fma2(o2[0][1], pp, b23); \
                pp = fdup(p1.PM); fma2(o2[1][0], pp, b01); fma2(o2[1][1], pp, b23); \
                pp = fdup(p2.PM); fma2(o2[2][0], pp, b01); fma2(o2[2][1], pp, b23); \
                pp = fdup(p3.PM); fma2(o2[3][0], pp, b01); fma2(o2[3][1], pp, b23); }
                PB(v0, x) PB(v1, y) PB(v2, z) PB(v3, w)
#undef PB
            }
        }

        // ---- epilogue: write partial O and l (reduce l once per q-tile) ----
#pragma unroll
        for (int i = 0; i < 4; i++) {
            float rs = l_i[i];
            rs += __shfl_xor_sync(0xffffffffu, rs, 8);
            rs += __shfl_xor_sync(0xffffffffu, rs, 4);
            rs += __shfl_xor_sync(0xffffffffu, rs, 2);
            rs += __shfl_xor_sync(0xffffffffu, rs, 1);
            int row = b * TT + qBase + r_[i];
            if (tx == 0) g_l[z][row] = rs;
            float4 v;
            f2up(o2[i][0], v.x, v.y);
            f2up(o2[i][1], v.z, v.w);
            *(float4*)&g_po[z][(size_t)row * HH + tx * 4] = v;
        }
    }
}

// ---------------------------------------------------------------------------
// Combine: out = (O0 + O1) / (l0 + l1)
// ---------------------------------------------------------------------------
__global__ __launch_bounds__(256) void combine(float* __restrict__ outp)
{
    int idx = blockIdx.x * 256 + threadIdx.x;     // f4 index, 0..262143
    int row = idx >> 4;
    float inv = 1.0f / (g_l[0][row] + g_l[1][row]);
    float4 a = ((const float4*)g_po[0])[idx];
    float4 c = ((const float4*)g_po[1])[idx];
    float4 o;
    o.x = (a.x + c.x) * inv;
    o.y = (a.y + c.y) * inv;
    o.z = (a.z + c.z) * inv;
    o.w = (a.w + c.w) * inv;
    ((float4*)outp)[idx] = o;
}

// ---------------------------------------------------------------------------
extern "C" void kernel_launch(void* const* d_in, const int* in_sizes, int n_in,
                              void* d_out, int out_size)
{
    const float* x     = (const float*)d_in[0];
    const float* Wq    = (const float*)d_in[1];
    const float* Wk    = (const float*)d_in[2];
    const float* Wv    = (const float*)d_in[3];
    const float* rbias = (const float*)d_in[4];
    // d_in[5] = allowed: reconstructed from rbias + diagonal + causal
    float* outp = (float*)d_out;

    qkv_gemm<<<128, 256>>>(x, Wq, Wk, Wv);
    attn<<<dim3(16, 8, 2), 256>>>(rbias);
    combine<<<(BB * TT * HH / 4) / 256, 256>>>(outp);
}